// round 16
// baseline (speedup 1.0000x reference)
#include <cuda_runtime.h>
#include <cuda_fp16.h>
#include <stdint.h>

#define DM    1024
#define NH    16
#define DKH   64
#define BATCH 2
#define SEQ   2048
#define MTOT  (BATCH*SEQ)   // 4096

typedef __half f16;

// ---------------- scratch (no allocations allowed) ----------------
__device__ f16 g_xh[MTOT*DM],  g_xl[MTOT*DM];
__device__ f16 g_wqh[DM*DM];
__device__ f16 g_wkh[DM*DM];
__device__ f16 g_wvh[DM*DM];
__device__ f16 g_woh[DM*DM];
__device__ f16 g_Qh[MTOT*DM], g_Ql[MTOT*DM];
__device__ f16 g_Kh[MTOT*DM];
__device__ f16 g_Vh[MTOT*DM];
__device__ f16 g_Ch[MTOT*DM];

// ---------------- helpers ----------------
__device__ __forceinline__ uint32_t smem_u32(const void* p){
    uint32_t a;
    asm("{ .reg .u64 t; cvta.to.shared.u64 t, %1; cvt.u32.u64 %0, t; }" : "=r"(a) : "l"(p));
    return a;
}
__device__ __forceinline__ void ldm4(uint32_t* d, uint32_t a){
    asm volatile("ldmatrix.sync.aligned.m8n8.x4.shared.b16 {%0,%1,%2,%3},[%4];"
        : "=r"(d[0]),"=r"(d[1]),"=r"(d[2]),"=r"(d[3]) : "r"(a));
}
__device__ __forceinline__ void ldm4t(uint32_t* d, uint32_t a){
    asm volatile("ldmatrix.sync.aligned.m8n8.x4.trans.shared.b16 {%0,%1,%2,%3},[%4];"
        : "=r"(d[0]),"=r"(d[1]),"=r"(d[2]),"=r"(d[3]) : "r"(a));
}
__device__ __forceinline__ void mma_f16(float* c,
    uint32_t a0,uint32_t a1,uint32_t a2,uint32_t a3, uint32_t b0,uint32_t b1){
    asm volatile(
      "mma.sync.aligned.m16n8k16.row.col.f32.f16.f16.f32 "
      "{%0,%1,%2,%3},{%4,%5,%6,%7},{%8,%9},{%0,%1,%2,%3};\n"
      : "+f"(c[0]),"+f"(c[1]),"+f"(c[2]),"+f"(c[3])
      : "r"(a0),"r"(a1),"r"(a2),"r"(a3),"r"(b0),"r"(b1));
}
__device__ __forceinline__ void cpa16(uint32_t dst, const void* src){
    asm volatile("cp.async.cg.shared.global [%0],[%1],16;\n" :: "r"(dst),"l"(src));
}
__device__ __forceinline__ void cpa_commit(){ asm volatile("cp.async.commit_group;\n" ::: "memory"); }
template<int NN> __device__ __forceinline__ void cpa_wait(){
    asm volatile("cp.async.wait_group %0;\n" :: "n"(NN) : "memory");
}

// fp32 pair -> (hi, lo) fp16 pairs.  hi = rn(v), lo = rn(v - hi).
__device__ __forceinline__ void split2f16(float v0, float v1, uint32_t& h01, uint32_t& l01){
    __half2 h2 = __floats2half2_rn(v0, v1);
    float2 hf = __half22float2(h2);
    __half2 l2 = __floats2half2_rn(v0 - hf.x, v1 - hf.y);
    h01 = *(uint32_t*)&h2;
    l01 = *(uint32_t*)&l2;
}
__device__ __forceinline__ uint32_t pack2f16(float v0, float v1){
    __half2 h2 = __floats2half2_rn(v0, v1);
    return *(uint32_t*)&h2;
}

// ---------------- split kernels ----------------
__global__ void split_kernel(const float* __restrict__ in,
                             f16* __restrict__ hi, f16* __restrict__ lo, int n){
    int i = (blockIdx.x * blockDim.x + threadIdx.x) * 4;
    if (i >= n) return;
    float4 v = *(const float4*)(in + i);
    uint2 hh, ll;
    split2f16(v.x, v.y, hh.x, ll.x);
    split2f16(v.z, v.w, hh.y, ll.y);
    *(uint2*)(hi + i) = hh;
    *(uint2*)(lo + i) = ll;
}

__global__ void split4_hi_kernel(const float* __restrict__ w0, const float* __restrict__ w1,
                                 const float* __restrict__ w2, const float* __restrict__ w3,
                                 f16* __restrict__ h0, f16* __restrict__ h1,
                                 f16* __restrict__ h2, f16* __restrict__ h3){
    const float* in; f16* hi;
    switch (blockIdx.y){
        case 0: in = w0; hi = h0; break;
        case 1: in = w1; hi = h1; break;
        case 2: in = w2; hi = h2; break;
        default: in = w3; hi = h3; break;
    }
    int i = (blockIdx.x * blockDim.x + threadIdx.x) * 4;
    if (i >= DM*DM) return;
    float4 v = *(const float4*)(in + i);
    uint2 hh;
    hh.x = pack2f16(v.x, v.y);
    hh.y = pack2f16(v.z, v.w);
    *(uint2*)(hi + i) = hh;
}

// =============================================================
// fp16 MMA GEMM, cp.async double-buffer, K-chunk 64, pitch 72 (R15, best).
// NPASS=2: C = (Ah+Al)*Wh^T + b.  NPASS=1: C = Ah*Wh^T + b.
// MODE 0: fp32 out.  MODE 1: split fp16 h+l out, *scale.  MODE 2: hi out, *scale.
// =============================================================
#define GBM 128
#define GBN 128
#define GBK 64
#define GAP 72
#define GARR_B (GBM*GAP*2)          // 18432 bytes per array
#define GSTG_B (3*GARR_B)           // 55296 bytes per stage
#define GOFF_AH 0
#define GOFF_AL (1*GARR_B)
#define GOFF_WH (2*GARR_B)
#define GEMM_SMEM (2*GSTG_B)        // 110592 bytes

template<int NPASS>
__device__ __forceinline__ void gemm_load_chunk(
    uint32_t sbase,
    const f16* __restrict__ Ah, const f16* __restrict__ Al,
    const f16* __restrict__ Wh,
    int bm, int bn, int k0, int tid, int K)
{
    #pragma unroll
    for (int i = 0; i < 4; i++){
        int idx = tid + i*256;
        int r = idx >> 3, s = idx & 7;
        uint32_t d = (uint32_t)(r*144 + s*16);
        const size_t ga = (size_t)(bm + r)*K + k0 + s*8;
        const size_t gw = (size_t)(bn + r)*K + k0 + s*8;
        cpa16(sbase + GOFF_AH + d, Ah + ga);
        if (NPASS == 2) cpa16(sbase + GOFF_AL + d, Al + ga);
        cpa16(sbase + GOFF_WH + d, Wh + gw);
    }
}

template<int MODE, int NPASS>
__global__ __launch_bounds__(256, 2) void gemm_mma(
    const f16* __restrict__ Ah, const f16* __restrict__ Al,
    const f16* __restrict__ Wh,
    const float* __restrict__ bias,
    float* __restrict__ Cf, f16* __restrict__ Ch, f16* __restrict__ Cl,
    int M, int N, int K, float scale)
{
    extern __shared__ f16 gsm[];
    const uint32_t sb = smem_u32(gsm);

    const int tid  = threadIdx.x;
    const int wid  = tid >> 5;
    const int lane = tid & 31;
    const int bm   = blockIdx.y * GBM;
    const int bn   = blockIdx.x * GBN;
    const int mwb  = (wid >> 2) * 64;
    const int nwb  = (wid & 3) * 32;

    const int g = lane >> 3, r = lane & 7;
    const uint32_t oA = (uint32_t)((mwb + (g&1)*8 + r)*GAP + (g>>1)*8)*2;
    const uint32_t oW = (uint32_t)((nwb + (g>>1)*8 + r)*GAP + (g&1)*8)*2;

    float acc[4][4][4];
    #pragma unroll
    for (int i = 0; i < 4; i++) {
        #pragma unroll
        for (int j = 0; j < 4; j++) {
            #pragma unroll
            for (int q = 0; q < 4; q++) acc[i][j][q] = 0.f;
        }
    }

    gemm_load_chunk<NPASS>(sb,          Ah, Al, Wh, bm, bn, 0,   tid, K); cpa_commit();
    gemm_load_chunk<NPASS>(sb + GSTG_B, Ah, Al, Wh, bm, bn, GBK, tid, K); cpa_commit();

    const int nst = K / GBK;   // 16
    #pragma unroll 1
    for (int s = 0; s < nst; s++){
        if (s + 1 < nst) cpa_wait<1>(); else cpa_wait<0>();
        __syncthreads();

        const uint32_t stg = sb + (uint32_t)(s & 1) * GSTG_B;
        const uint32_t aAh = stg + GOFF_AH + oA;
        const uint32_t aAl = stg + GOFF_AL + oA;
        const uint32_t aWh = stg + GOFF_WH + oW;

        #pragma unroll
        for (int kc = 0; kc < 4; kc++){
            uint32_t ah[4][4], al[4][4];
            #pragma unroll
            for (int i = 0; i < 4; i++){
                ldm4(ah[i], aAh + (uint32_t)(i*16*GAP)*2 + kc*32);
                if (NPASS == 2) ldm4(al[i], aAl + (uint32_t)(i*16*GAP)*2 + kc*32);
            }
            #pragma unroll
            for (int jp = 0; jp < 2; jp++){
                uint32_t bh[4];
                ldm4(bh, aWh + (uint32_t)(jp*16*GAP)*2 + kc*32);
                #pragma unroll
                for (int hh = 0; hh < 2; hh++){
                    const int f = jp*2 + hh;
                    #pragma unroll
                    for (int i = 0; i < 4; i++){
                        mma_f16(acc[i][f], ah[i][0],ah[i][1],ah[i][2],ah[i][3], bh[2*hh], bh[2*hh+1]);
                        if (NPASS == 2)
                            mma_f16(acc[i][f], al[i][0],al[i][1],al[i][2],al[i][3], bh[2*hh], bh[2*hh+1]);
                    }
                }
            }
        }
        __syncthreads();

        if (s + 2 < nst){
            gemm_load_chunk<NPASS>(stg, Ah, Al, Wh, bm, bn, (s+2)*GBK, tid, K);
            cpa_commit();
        }
    }

    #pragma unroll
    for (int f = 0; f < 4; f++){
        const int c = bn + nwb + f*8 + (lane&3)*2;
        const float b0 = bias[c], b1 = bias[c+1];
        #pragma unroll
        for (int i = 0; i < 4; i++){
            const int r0 = bm + mwb + i*16 + (lane>>2);
            const int r1 = r0 + 8;
            float v00 = acc[i][f][0] + b0, v01 = acc[i][f][1] + b1;
            float v10 = acc[i][f][2] + b0, v11 = acc[i][f][3] + b1;
            if (MODE == 0){
                *(float2*)(Cf + (size_t)r0*N + c) = make_float2(v00, v01);
                *(float2*)(Cf + (size_t)r1*N + c) = make_float2(v10, v11);
            } else if (MODE == 1){
                uint32_t h01, l01;
                split2f16(v00*scale, v01*scale, h01, l01);
                *(uint32_t*)(Ch + (size_t)r0*N + c) = h01;
                *(uint32_t*)(Cl + (size_t)r0*N + c) = l01;
                split2f16(v10*scale, v11*scale, h01, l01);
                *(uint32_t*)(Ch + (size_t)r1*N + c) = h01;
                *(uint32_t*)(Cl + (size_t)r1*N + c) = l01;
            } else {
                *(uint32_t*)(Ch + (size_t)r0*N + c) = pack2f16(v00*scale, v01*scale);
                *(uint32_t*)(Ch + (size_t)r1*N + c) = pack2f16(v10*scale, v11*scale);
            }
        }
    }
}

// =============================================================
// Attention: S=(Qh+Ql)Kh^T (2-pass), P=exp(S) fp16, ctx=P Vh (1-pass).
// NEW: 128-row KV stages (2 x 64-row compute halves per stage) ->
// barriers halve (64 -> 32) with unchanged register pressure.
// Double-buffered; Q overlays stage 0; 73.7KB -> 2 CTAs/SM.
// =============================================================
#define BQ 128
#define BTS 128                          // rows per KV stage
#define AP 72
#define Q_ARR_B  (BQ*AP*2)               // 18432 B per Q array
#define KV_ARR_B (BTS*AP*2)              // 18432 B per array (Kh or Vh, 128 rows)
#define KV_STG_B (2*KV_ARR_B)            // 36864 B per stage
#define ATTN_SMEM (2*KV_STG_B)           // 73728 B
#define HBLK_B (64*AP*2)                 // byte offset of second 64-row half

__global__ __launch_bounds__(256, 2) void attn_mma(
    const f16* __restrict__ Qh, const f16* __restrict__ Ql,
    const f16* __restrict__ Kh,
    const f16* __restrict__ Vh,
    f16* __restrict__ Ch)
{
    extern __shared__ f16 sm[];
    const uint32_t base = smem_u32(sm);
    const uint32_t qh_b = base;                 // overlays stage-0 K region
    const uint32_t ql_b = base + Q_ARR_B;       // overlays stage-0 V region
    const uint32_t kv_b = base;

    const int tid  = threadIdx.x;
    const int wid  = tid >> 5;
    const int lane = tid & 31;
    const int b = blockIdx.z, h = blockIdx.y;
    const int q0 = blockIdx.x * BQ;
    const size_t hb = ((size_t)b * SEQ) * DM + (size_t)h * DKH;

    const int g = lane >> 3, r = lane & 7;
    const uint32_t aQh = qh_b + (uint32_t)((wid*16 + (g&1)*8 + r)*AP + (g>>1)*8)*2;
    const uint32_t aQl = ql_b + (uint32_t)((wid*16 + (g&1)*8 + r)*AP + (g>>1)*8)*2;
    const uint32_t oK  = (uint32_t)(((g>>1)*8 + r)*AP + (g&1)*8)*2;
    const uint32_t oV  = (uint32_t)(((g&1)*8 + r)*AP + (g>>1)*8)*2;

    // ---- Phase 1: stage Q (h+l) in overlaid smem, pull fragments to regs ----
    #pragma unroll
    for (int i = 0; i < 4; i++){
        int idx = tid + i*256;
        int row = idx >> 3, seg = idx & 7;
        size_t go = hb + (size_t)(q0 + row)*DM + seg*8;
        uint32_t d = (uint32_t)(row*AP + seg*8)*2;
        cpa16(qh_b + d, Qh + go);
        cpa16(ql_b + d, Ql + go);
    }
    cpa_commit();
    cpa_wait<0>();
    __syncthreads();

    uint32_t qfh[4][4], qfl[4][4];
    #pragma unroll
    for (int kc = 0; kc < 4; kc++){
        ldm4(qfh[kc], aQh + kc*32);
        ldm4(qfl[kc], aQl + kc*32);
    }
    __syncthreads();   // Q smem free; KV ring may overwrite

    // ---- Phase 2: load stage 0 (rows 0..127 of K,V) ----
    #pragma unroll
    for (int i = 0; i < 4; i++){
        int idx = tid + i*256;             // 0..1023
        int row = idx >> 3, seg = idx & 7;
        size_t go = hb + (size_t)row*DM + seg*8;
        uint32_t d = kv_b + (uint32_t)(row*AP + seg*8)*2;
        cpa16(d + 0*KV_ARR_B, Kh + go);
        cpa16(d + 1*KV_ARR_B, Vh + go);
    }
    cpa_commit();

    float o[8][4];
    #pragma unroll
    for (int f = 0; f < 8; f++){
        #pragma unroll
        for (int q = 0; q < 4; q++) o[f][q] = 0.f;
    }
    float dr0 = 0.f, dr1 = 0.f;

    const int NT = SEQ / BTS;   // 16
    #pragma unroll 1
    for (int t = 0; t < NT; t++){
        const uint32_t sb = kv_b + (uint32_t)(t & 1) * KV_STG_B;

        if (t + 1 < NT){
            const uint32_t nb = kv_b + (uint32_t)((t+1) & 1) * KV_STG_B;
            const int t0n = (t+1) * BTS;
            #pragma unroll
            for (int i = 0; i < 4; i++){
                int idx = tid + i*256;
                int row = idx >> 3, seg = idx & 7;
                size_t go = hb + (size_t)(t0n + row)*DM + seg*8;
                uint32_t d = nb + (uint32_t)(row*AP + seg*8)*2;
                cpa16(d + 0*KV_ARR_B, Kh + go);
                cpa16(d + 1*KV_ARR_B, Vh + go);
            }
            cpa_commit();
            cpa_wait<1>();
        } else {
            cpa_wait<0>();
        }
        __syncthreads();

        // two 64-row compute halves, same registers reused
        #pragma unroll
        for (int h2 = 0; h2 < 2; h2++){
            const uint32_t hb2 = (uint32_t)h2 * HBLK_B;
            const uint32_t aKh = sb + 0*KV_ARR_B + hb2 + oK;
            const uint32_t aVh = sb + 1*KV_ARR_B + hb2 + oV;

            // S = (Qh+Ql) Kh^T  (2-pass)
            float s[8][4];
            #pragma unroll
            for (int f = 0; f < 8; f++){
                #pragma unroll
                for (int q = 0; q < 4; q++) s[f][q] = 0.f;
            }
            #pragma unroll
            for (int kc = 0; kc < 4; kc++){
                #pragma unroll
                for (int jp = 0; jp < 4; jp++){
                    uint32_t kbh[4];
                    ldm4(kbh, aKh + (uint32_t)(jp*16*AP)*2 + kc*32);
                    #pragma unroll
                    for (int hh = 0; hh < 2; hh++){
                        const int f = jp*2 + hh;
                        mma_f16(s[f], qfh[kc][0],qfh[kc][1],qfh[kc][2],qfh[kc][3], kbh[2*hh], kbh[2*hh+1]);
                        mma_f16(s[f], qfl[kc][0],qfl[kc][1],qfl[kc][2],qfl[kc][3], kbh[2*hh], kbh[2*hh+1]);
                    }
                }
            }

            // P = exp(S): rowsums + fp16 hi pack
            uint32_t ph[8][2];
            #pragma unroll
            for (int f = 0; f < 8; f++){
                float p0 = __expf(s[f][0]), p1 = __expf(s[f][1]);
                float p2 = __expf(s[f][2]), p3 = __expf(s[f][3]);
                dr0 += p0 + p1;  dr1 += p2 + p3;
                ph[f][0] = pack2f16(p0, p1);
                ph[f][1] = pack2f16(p2, p3);
            }

            // ctx += Ph Vh  (1-pass)
            #pragma unroll
            for (int kc = 0; kc < 4; kc++){
                const uint32_t ah0 = ph[2*kc][0], ah1 = ph[2*kc][1];
                const uint32_t ah2 = ph[2*kc+1][0], ah3 = ph[2*kc+1][1];
                #pragma unroll
                for (int jp = 0; jp < 4; jp++){
                    uint32_t vbh[4];
                    ldm4t(vbh, aVh + (uint32_t)(kc*16*AP)*2 + jp*32);
                    #pragma unroll
                    for (int hh = 0; hh < 2; hh++){
                        const int f = jp*2 + hh;
                        mma_f16(o[f], ah0,ah1,ah2,ah3, vbh[2*hh], vbh[2*hh+1]);
                    }
                }
            }
        }
        __syncthreads();
    }

    float d0 = dr0, d1 = dr1;
    d0 += __shfl_xor_sync(0xffffffffu, d0, 1);
    d0 += __shfl_xor_sync(0xffffffffu, d0, 2);
    d1 += __shfl_xor_sync(0xffffffffu, d1, 1);
    d1 += __shfl_xor_sync(0xffffffffu, d1, 2);
    const float inv0 = 1.0f / d0, inv1 = 1.0f / d1;

    const int r0 = q0 + wid*16 + (lane>>2);
    const int r1 = r0 + 8;
    #pragma unroll
    for (int f = 0; f < 8; f++){
        const int c = f*8 + (lane&3)*2;
        *(uint32_t*)(Ch + hb + (size_t)r0*DM + c) = pack2f16(o[f][0]*inv0, o[f][1]*inv0);
        *(uint32_t*)(Ch + hb + (size_t)r1*DM + c) = pack2f16(o[f][2]*inv1, o[f][3]*inv1);
    }
}

// =============================================================
// launch
// =============================================================
extern "C" void kernel_launch(void* const* d_in, const int* in_sizes, int n_in,
                              void* d_out, int out_size)
{
    const float* x  = (const float*)d_in[0];
    const float* Wq = (const float*)d_in[1];
    const float* bq = (const float*)d_in[2];
    const float* Wk = (const float*)d_in[3];
    const float* bk = (const float*)d_in[4];
    const float* Wv = (const float*)d_in[5];
    const float* bv = (const float*)d_in[6];
    const float* Wo = (const float*)d_in[7];
    const float* bo = (const float*)d_in[8];
    float* out = (float*)d_out;

    f16 *xh,*xl,*wqh,*wkh,*wvh,*woh;
    f16 *qhp,*qlp,*khp,*vhp,*chp;
    cudaGetSymbolAddress((void**)&xh,  g_xh);  cudaGetSymbolAddress((void**)&xl,  g_xl);
    cudaGetSymbolAddress((void**)&wqh, g_wqh);
    cudaGetSymbolAddress((void**)&wkh, g_wkh);
    cudaGetSymbolAddress((void**)&wvh, g_wvh);
    cudaGetSymbolAddress((void**)&woh, g_woh);
    cudaGetSymbolAddress((void**)&qhp, g_Qh);  cudaGetSymbolAddress((void**)&qlp, g_Ql);
    cudaGetSymbolAddress((void**)&khp, g_Kh);
    cudaGetSymbolAddress((void**)&vhp, g_Vh);
    cudaGetSymbolAddress((void**)&chp, g_Ch);

    cudaFuncSetAttribute(attn_mma, cudaFuncAttributeMaxDynamicSharedMemorySize, ATTN_SMEM);
    cudaFuncSetAttribute((gemm_mma<1,2>), cudaFuncAttributeMaxDynamicSharedMemorySize, GEMM_SMEM);
    cudaFuncSetAttribute((gemm_mma<2,2>), cudaFuncAttributeMaxDynamicSharedMemorySize, GEMM_SMEM);
    cudaFuncSetAttribute((gemm_mma<2,1>), cudaFuncAttributeMaxDynamicSharedMemorySize, GEMM_SMEM);
    cudaFuncSetAttribute((gemm_mma<0,1>), cudaFuncAttributeMaxDynamicSharedMemorySize, GEMM_SMEM);

    split_kernel<<<(MTOT*DM/4 + 255)/256, 256>>>(x, xh, xl, MTOT*DM);
    {
        dim3 gs((DM*DM/4 + 255)/256, 4);
        split4_hi_kernel<<<gs, 256>>>(Wq, Wk, Wv, Wo, wqh, wkh, wvh, woh);
    }

    dim3 gg(DM/GBN, MTOT/GBM);   // (8, 32)
    const float qscale = 0.125f; // 1/sqrt(64)
    gemm_mma<1,2><<<gg, 256, GEMM_SMEM>>>(xh, xl, wqh, bq, nullptr, qhp, qlp, MTOT, DM, DM, qscale);
    gemm_mma<2,2><<<gg, 256, GEMM_SMEM>>>(xh, xl, wkh, bk, nullptr, khp, nullptr, MTOT, DM, DM, 1.0f);
    gemm_mma<2,1><<<gg, 256, GEMM_SMEM>>>(xh, nullptr, wvh, bv, nullptr, vhp, nullptr, MTOT, DM, DM, 1.0f);

    dim3 ga(SEQ/BQ, NH, BATCH);  // (16, 16, 2)
    attn_mma<<<ga, 256, ATTN_SMEM>>>(qhp, qlp, khp, vhp, chp);

    gemm_mma<0,1><<<gg, 256, GEMM_SMEM>>>(chp, nullptr, woh, bo, out, nullptr, nullptr, MTOT, DM, DM, 1.0f);
}

// round 17
// speedup vs baseline: 1.0612x; 1.0612x over previous
#include <cuda_runtime.h>
#include <cuda_fp16.h>
#include <stdint.h>

#define DM    1024
#define NH    16
#define DKH   64
#define BATCH 2
#define SEQ   2048
#define MTOT  (BATCH*SEQ)   // 4096

typedef __half f16;

// ---------------- scratch (no allocations allowed) ----------------
__device__ f16 g_xh[MTOT*DM],  g_xl[MTOT*DM];
__device__ f16 g_wqh[DM*DM];
__device__ f16 g_wkh[DM*DM];
__device__ f16 g_wvh[DM*DM];
__device__ f16 g_woh[DM*DM];
__device__ f16 g_Qh[MTOT*DM], g_Ql[MTOT*DM];
__device__ f16 g_Kh[MTOT*DM];
__device__ f16 g_Vh[MTOT*DM];
__device__ f16 g_Ch[MTOT*DM];

// ---------------- helpers ----------------
__device__ __forceinline__ uint32_t smem_u32(const void* p){
    uint32_t a;
    asm("{ .reg .u64 t; cvta.to.shared.u64 t, %1; cvt.u32.u64 %0, t; }" : "=r"(a) : "l"(p));
    return a;
}
__device__ __forceinline__ void ldm4(uint32_t* d, uint32_t a){
    asm volatile("ldmatrix.sync.aligned.m8n8.x4.shared.b16 {%0,%1,%2,%3},[%4];"
        : "=r"(d[0]),"=r"(d[1]),"=r"(d[2]),"=r"(d[3]) : "r"(a));
}
__device__ __forceinline__ void ldm4t(uint32_t* d, uint32_t a){
    asm volatile("ldmatrix.sync.aligned.m8n8.x4.trans.shared.b16 {%0,%1,%2,%3},[%4];"
        : "=r"(d[0]),"=r"(d[1]),"=r"(d[2]),"=r"(d[3]) : "r"(a));
}
__device__ __forceinline__ void mma_f16(float* c,
    uint32_t a0,uint32_t a1,uint32_t a2,uint32_t a3, uint32_t b0,uint32_t b1){
    asm volatile(
      "mma.sync.aligned.m16n8k16.row.col.f32.f16.f16.f32 "
      "{%0,%1,%2,%3},{%4,%5,%6,%7},{%8,%9},{%0,%1,%2,%3};\n"
      : "+f"(c[0]),"+f"(c[1]),"+f"(c[2]),"+f"(c[3])
      : "r"(a0),"r"(a1),"r"(a2),"r"(a3),"r"(b0),"r"(b1));
}
__device__ __forceinline__ void cpa16(uint32_t dst, const void* src){
    asm volatile("cp.async.cg.shared.global [%0],[%1],16;\n" :: "r"(dst),"l"(src));
}
__device__ __forceinline__ void cpa_commit(){ asm volatile("cp.async.commit_group;\n" ::: "memory"); }
template<int NN> __device__ __forceinline__ void cpa_wait(){
    asm volatile("cp.async.wait_group %0;\n" :: "n"(NN) : "memory");
}

// fp32 pair -> (hi, lo) fp16 pairs.  hi = rn(v), lo = rn(v - hi).
__device__ __forceinline__ void split2f16(float v0, float v1, uint32_t& h01, uint32_t& l01){
    __half2 h2 = __floats2half2_rn(v0, v1);
    float2 hf = __half22float2(h2);
    __half2 l2 = __floats2half2_rn(v0 - hf.x, v1 - hf.y);
    h01 = *(uint32_t*)&h2;
    l01 = *(uint32_t*)&l2;
}
__device__ __forceinline__ uint32_t pack2f16(float v0, float v1){
    __half2 h2 = __floats2half2_rn(v0, v1);
    return *(uint32_t*)&h2;
}

// ---------------- split kernels ----------------
__global__ void split_kernel(const float* __restrict__ in,
                             f16* __restrict__ hi, f16* __restrict__ lo, int n){
    int i = (blockIdx.x * blockDim.x + threadIdx.x) * 4;
    if (i >= n) return;
    float4 v = *(const float4*)(in + i);
    uint2 hh, ll;
    split2f16(v.x, v.y, hh.x, ll.x);
    split2f16(v.z, v.w, hh.y, ll.y);
    *(uint2*)(hi + i) = hh;
    *(uint2*)(lo + i) = ll;
}

__global__ void split4_hi_kernel(const float* __restrict__ w0, const float* __restrict__ w1,
                                 const float* __restrict__ w2, const float* __restrict__ w3,
                                 f16* __restrict__ h0, f16* __restrict__ h1,
                                 f16* __restrict__ h2, f16* __restrict__ h3){
    const float* in; f16* hi;
    switch (blockIdx.y){
        case 0: in = w0; hi = h0; break;
        case 1: in = w1; hi = h1; break;
        case 2: in = w2; hi = h2; break;
        default: in = w3; hi = h3; break;
    }
    int i = (blockIdx.x * blockDim.x + threadIdx.x) * 4;
    if (i >= DM*DM) return;
    float4 v = *(const float4*)(in + i);
    uint2 hh;
    hh.x = pack2f16(v.x, v.y);
    hh.y = pack2f16(v.z, v.w);
    *(uint2*)(hi + i) = hh;
}

// =============================================================
// fp16 MMA GEMM, cp.async double-buffer, K-chunk 64, pitch 72 (R15, best).
// NPASS=2: C = (Ah+Al)*Wh^T + b.  NPASS=1: C = Ah*Wh^T + b.
// MODE 0: fp32 out.  MODE 1: split fp16 h+l out, *scale.  MODE 2: hi out, *scale.
// =============================================================
#define GBM 128
#define GBN 128
#define GBK 64
#define GAP 72
#define GARR_B (GBM*GAP*2)          // 18432 bytes per array
#define GSTG_B (3*GARR_B)           // 55296 bytes per stage
#define GOFF_AH 0
#define GOFF_AL (1*GARR_B)
#define GOFF_WH (2*GARR_B)
#define GEMM_SMEM (2*GSTG_B)        // 110592 bytes

template<int NPASS>
__device__ __forceinline__ void gemm_load_chunk(
    uint32_t sbase,
    const f16* __restrict__ Ah, const f16* __restrict__ Al,
    const f16* __restrict__ Wh,
    int bm, int bn, int k0, int tid, int K)
{
    #pragma unroll
    for (int i = 0; i < 4; i++){
        int idx = tid + i*256;
        int r = idx >> 3, s = idx & 7;
        uint32_t d = (uint32_t)(r*144 + s*16);
        const size_t ga = (size_t)(bm + r)*K + k0 + s*8;
        const size_t gw = (size_t)(bn + r)*K + k0 + s*8;
        cpa16(sbase + GOFF_AH + d, Ah + ga);
        if (NPASS == 2) cpa16(sbase + GOFF_AL + d, Al + ga);
        cpa16(sbase + GOFF_WH + d, Wh + gw);
    }
}

template<int MODE, int NPASS>
__global__ __launch_bounds__(256, 2) void gemm_mma(
    const f16* __restrict__ Ah, const f16* __restrict__ Al,
    const f16* __restrict__ Wh,
    const float* __restrict__ bias,
    float* __restrict__ Cf, f16* __restrict__ Ch, f16* __restrict__ Cl,
    int M, int N, int K, float scale)
{
    extern __shared__ f16 gsm[];
    const uint32_t sb = smem_u32(gsm);

    const int tid  = threadIdx.x;
    const int wid  = tid >> 5;
    const int lane = tid & 31;
    const int bm   = blockIdx.y * GBM;
    const int bn   = blockIdx.x * GBN;
    const int mwb  = (wid >> 2) * 64;
    const int nwb  = (wid & 3) * 32;

    const int g = lane >> 3, r = lane & 7;
    const uint32_t oA = (uint32_t)((mwb + (g&1)*8 + r)*GAP + (g>>1)*8)*2;
    const uint32_t oW = (uint32_t)((nwb + (g>>1)*8 + r)*GAP + (g&1)*8)*2;

    float acc[4][4][4];
    #pragma unroll
    for (int i = 0; i < 4; i++) {
        #pragma unroll
        for (int j = 0; j < 4; j++) {
            #pragma unroll
            for (int q = 0; q < 4; q++) acc[i][j][q] = 0.f;
        }
    }

    gemm_load_chunk<NPASS>(sb,          Ah, Al, Wh, bm, bn, 0,   tid, K); cpa_commit();
    gemm_load_chunk<NPASS>(sb + GSTG_B, Ah, Al, Wh, bm, bn, GBK, tid, K); cpa_commit();

    const int nst = K / GBK;   // 16
    #pragma unroll 1
    for (int s = 0; s < nst; s++){
        if (s + 1 < nst) cpa_wait<1>(); else cpa_wait<0>();
        __syncthreads();

        const uint32_t stg = sb + (uint32_t)(s & 1) * GSTG_B;
        const uint32_t aAh = stg + GOFF_AH + oA;
        const uint32_t aAl = stg + GOFF_AL + oA;
        const uint32_t aWh = stg + GOFF_WH + oW;

        #pragma unroll
        for (int kc = 0; kc < 4; kc++){
            uint32_t ah[4][4], al[4][4];
            #pragma unroll
            for (int i = 0; i < 4; i++){
                ldm4(ah[i], aAh + (uint32_t)(i*16*GAP)*2 + kc*32);
                if (NPASS == 2) ldm4(al[i], aAl + (uint32_t)(i*16*GAP)*2 + kc*32);
            }
            #pragma unroll
            for (int jp = 0; jp < 2; jp++){
                uint32_t bh[4];
                ldm4(bh, aWh + (uint32_t)(jp*16*GAP)*2 + kc*32);
                #pragma unroll
                for (int hh = 0; hh < 2; hh++){
                    const int f = jp*2 + hh;
                    #pragma unroll
                    for (int i = 0; i < 4; i++){
                        mma_f16(acc[i][f], ah[i][0],ah[i][1],ah[i][2],ah[i][3], bh[2*hh], bh[2*hh+1]);
                        if (NPASS == 2)
                            mma_f16(acc[i][f], al[i][0],al[i][1],al[i][2],al[i][3], bh[2*hh], bh[2*hh+1]);
                    }
                }
            }
        }
        __syncthreads();

        if (s + 2 < nst){
            gemm_load_chunk<NPASS>(stg, Ah, Al, Wh, bm, bn, (s+2)*GBK, tid, K);
            cpa_commit();
        }
    }

    #pragma unroll
    for (int f = 0; f < 4; f++){
        const int c = bn + nwb + f*8 + (lane&3)*2;
        const float b0 = bias[c], b1 = bias[c+1];
        #pragma unroll
        for (int i = 0; i < 4; i++){
            const int r0 = bm + mwb + i*16 + (lane>>2);
            const int r1 = r0 + 8;
            float v00 = acc[i][f][0] + b0, v01 = acc[i][f][1] + b1;
            float v10 = acc[i][f][2] + b0, v11 = acc[i][f][3] + b1;
            if (MODE == 0){
                *(float2*)(Cf + (size_t)r0*N + c) = make_float2(v00, v01);
                *(float2*)(Cf + (size_t)r1*N + c) = make_float2(v10, v11);
            } else if (MODE == 1){
                uint32_t h01, l01;
                split2f16(v00*scale, v01*scale, h01, l01);
                *(uint32_t*)(Ch + (size_t)r0*N + c) = h01;
                *(uint32_t*)(Cl + (size_t)r0*N + c) = l01;
                split2f16(v10*scale, v11*scale, h01, l01);
                *(uint32_t*)(Ch + (size_t)r1*N + c) = h01;
                *(uint32_t*)(Cl + (size_t)r1*N + c) = l01;
            } else {
                *(uint32_t*)(Ch + (size_t)r0*N + c) = pack2f16(v00*scale, v01*scale);
                *(uint32_t*)(Ch + (size_t)r1*N + c) = pack2f16(v10*scale, v11*scale);
            }
        }
    }
}

// =============================================================
// Attention (R15/R12 proven version): S=(Qh+Ql)Kh^T (2-pass),
// P=exp(S) fp16, ctx=P Vh (1-pass). 64-row KV tiles, double-buffered.
// Q smem overlays KV ring; 2 CTAs/SM.
// =============================================================
#define BQ 128
#define BT 64
#define AP 72
#define Q_ELEMS  (BQ*AP)
#define Q_ARR_B  (Q_ELEMS*2)
#define KV_ELEMS (BT*AP)
#define KV_ARR_B (KV_ELEMS*2)
#define KV_STG_B (2*KV_ARR_B)
#define ATTN_SMEM (2*KV_STG_B)   // 36864 B

__global__ __launch_bounds__(256, 2) void attn_mma(
    const f16* __restrict__ Qh, const f16* __restrict__ Ql,
    const f16* __restrict__ Kh,
    const f16* __restrict__ Vh,
    f16* __restrict__ Ch)
{
    extern __shared__ f16 sm[];
    const uint32_t base = smem_u32(sm);
    const uint32_t qh_b = base;
    const uint32_t ql_b = base + Q_ARR_B;
    const uint32_t kv_b = base;

    const int tid  = threadIdx.x;
    const int wid  = tid >> 5;
    const int lane = tid & 31;
    const int b = blockIdx.z, h = blockIdx.y;
    const int q0 = blockIdx.x * BQ;
    const size_t hb = ((size_t)b * SEQ) * DM + (size_t)h * DKH;

    const int g = lane >> 3, r = lane & 7;
    const uint32_t aQh = qh_b + (uint32_t)((wid*16 + (g&1)*8 + r)*AP + (g>>1)*8)*2;
    const uint32_t aQl = ql_b + (uint32_t)((wid*16 + (g&1)*8 + r)*AP + (g>>1)*8)*2;
    const uint32_t oK  = (uint32_t)(((g>>1)*8 + r)*AP + (g&1)*8)*2;
    const uint32_t oV  = (uint32_t)(((g&1)*8 + r)*AP + (g>>1)*8)*2;

    #pragma unroll
    for (int i = 0; i < 4; i++){
        int idx = tid + i*256;
        int row = idx >> 3, seg = idx & 7;
        size_t go = hb + (size_t)(q0 + row)*DM + seg*8;
        uint32_t d = (uint32_t)(row*AP + seg*8)*2;
        cpa16(qh_b + d, Qh + go);
        cpa16(ql_b + d, Ql + go);
    }
    cpa_commit();
    cpa_wait<0>();
    __syncthreads();

    uint32_t qfh[4][4], qfl[4][4];
    #pragma unroll
    for (int kc = 0; kc < 4; kc++){
        ldm4(qfh[kc], aQh + kc*32);
        ldm4(qfl[kc], aQl + kc*32);
    }
    __syncthreads();   // Q smem free; KV ring may overwrite

    #pragma unroll
    for (int i = 0; i < 2; i++){
        int idx = tid + i*256;
        int row = idx >> 3, seg = idx & 7;
        size_t go = hb + (size_t)row*DM + seg*8;
        uint32_t d = kv_b + (uint32_t)(row*AP + seg*8)*2;
        cpa16(d + 0*KV_ARR_B, Kh + go);
        cpa16(d + 1*KV_ARR_B, Vh + go);
    }
    cpa_commit();

    float o[8][4];
    #pragma unroll
    for (int f = 0; f < 8; f++){
        #pragma unroll
        for (int q = 0; q < 4; q++) o[f][q] = 0.f;
    }
    float dr0 = 0.f, dr1 = 0.f;

    for (int t = 0; t < SEQ/BT; t++){
        const uint32_t sb = kv_b + (uint32_t)(t & 1) * KV_STG_B;

        if (t + 1 < SEQ/BT){
            const uint32_t nb = kv_b + (uint32_t)((t+1) & 1) * KV_STG_B;
            const int t0n = (t+1) * BT;
            #pragma unroll
            for (int i = 0; i < 2; i++){
                int idx = tid + i*256;
                int row = idx >> 3, seg = idx & 7;
                size_t go = hb + (size_t)(t0n + row)*DM + seg*8;
                uint32_t d = nb + (uint32_t)(row*AP + seg*8)*2;
                cpa16(d + 0*KV_ARR_B, Kh + go);
                cpa16(d + 1*KV_ARR_B, Vh + go);
            }
            cpa_commit();
            cpa_wait<1>();
        } else {
            cpa_wait<0>();
        }
        __syncthreads();

        const uint32_t aKh = sb + 0*KV_ARR_B + oK;
        const uint32_t aVh = sb + 1*KV_ARR_B + oV;

        float s[8][4];
        #pragma unroll
        for (int f = 0; f < 8; f++){
            #pragma unroll
            for (int q = 0; q < 4; q++) s[f][q] = 0.f;
        }
        #pragma unroll
        for (int kc = 0; kc < 4; kc++){
            #pragma unroll
            for (int jp = 0; jp < 4; jp++){
                uint32_t kbh[4];
                ldm4(kbh, aKh + (uint32_t)(jp*16*AP)*2 + kc*32);
                #pragma unroll
                for (int hh = 0; hh < 2; hh++){
                    const int f = jp*2 + hh;
                    mma_f16(s[f], qfh[kc][0],qfh[kc][1],qfh[kc][2],qfh[kc][3], kbh[2*hh], kbh[2*hh+1]);
                    mma_f16(s[f], qfl[kc][0],qfl[kc][1],qfl[kc][2],qfl[kc][3], kbh[2*hh], kbh[2*hh+1]);
                }
            }
        }

        uint32_t ph[8][2];
        #pragma unroll
        for (int f = 0; f < 8; f++){
            float p0 = __expf(s[f][0]), p1 = __expf(s[f][1]);
            float p2 = __expf(s[f][2]), p3 = __expf(s[f][3]);
            dr0 += p0 + p1;  dr1 += p2 + p3;
            ph[f][0] = pack2f16(p0, p1);
            ph[f][1] = pack2f16(p2, p3);
        }

        #pragma unroll
        for (int kc = 0; kc < 4; kc++){
            const uint32_t ah0 = ph[2*kc][0], ah1 = ph[2*kc][1];
            const uint32_t ah2 = ph[2*kc+1][0], ah3 = ph[2*kc+1][1];
            #pragma unroll
            for (int jp = 0; jp < 4; jp++){
                uint32_t vbh[4];
                ldm4t(vbh, aVh + (uint32_t)(kc*16*AP)*2 + jp*32);
                #pragma unroll
                for (int hh = 0; hh < 2; hh++){
                    const int f = jp*2 + hh;
                    mma_f16(o[f], ah0,ah1,ah2,ah3, vbh[2*hh], vbh[2*hh+1]);
                }
            }
        }
        __syncthreads();
    }

    float d0 = dr0, d1 = dr1;
    d0 += __shfl_xor_sync(0xffffffffu, d0, 1);
    d0 += __shfl_xor_sync(0xffffffffu, d0, 2);
    d1 += __shfl_xor_sync(0xffffffffu, d1, 1);
    d1 += __shfl_xor_sync(0xffffffffu, d1, 2);
    const float inv0 = 1.0f / d0, inv1 = 1.0f / d1;

    const int r0 = q0 + wid*16 + (lane>>2);
    const int r1 = r0 + 8;
    #pragma unroll
    for (int f = 0; f < 8; f++){
        const int c = f*8 + (lane&3)*2;
        *(uint32_t*)(Ch + hb + (size_t)r0*DM + c) = pack2f16(o[f][0]*inv0, o[f][1]*inv0);
        *(uint32_t*)(Ch + hb + (size_t)r1*DM + c) = pack2f16(o[f][2]*inv1, o[f][3]*inv1);
    }
}

// =============================================================
// launch — Q/K/V projections overlapped on 3 streams (event fork/join,
// graph-capturable). Streams/events created once (correctness call,
// outside capture) and reused.
// =============================================================
extern "C" void kernel_launch(void* const* d_in, const int* in_sizes, int n_in,
                              void* d_out, int out_size)
{
    const float* x  = (const float*)d_in[0];
    const float* Wq = (const float*)d_in[1];
    const float* bq = (const float*)d_in[2];
    const float* Wk = (const float*)d_in[3];
    const float* bk = (const float*)d_in[4];
    const float* Wv = (const float*)d_in[5];
    const float* bv = (const float*)d_in[6];
    const float* Wo = (const float*)d_in[7];
    const float* bo = (const float*)d_in[8];
    float* out = (float*)d_out;

    f16 *xh,*xl,*wqh,*wkh,*wvh,*woh;
    f16 *qhp,*qlp,*khp,*vhp,*chp;
    cudaGetSymbolAddress((void**)&xh,  g_xh);  cudaGetSymbolAddress((void**)&xl,  g_xl);
    cudaGetSymbolAddress((void**)&wqh, g_wqh);
    cudaGetSymbolAddress((void**)&wkh, g_wkh);
    cudaGetSymbolAddress((void**)&wvh, g_wvh);
    cudaGetSymbolAddress((void**)&woh, g_woh);
    cudaGetSymbolAddress((void**)&qhp, g_Qh);  cudaGetSymbolAddress((void**)&qlp, g_Ql);
    cudaGetSymbolAddress((void**)&khp, g_Kh);
    cudaGetSymbolAddress((void**)&vhp, g_Vh);
    cudaGetSymbolAddress((void**)&chp, g_Ch);

    cudaFuncSetAttribute(attn_mma, cudaFuncAttributeMaxDynamicSharedMemorySize, ATTN_SMEM);
    cudaFuncSetAttribute((gemm_mma<1,2>), cudaFuncAttributeMaxDynamicSharedMemorySize, GEMM_SMEM);
    cudaFuncSetAttribute((gemm_mma<2,2>), cudaFuncAttributeMaxDynamicSharedMemorySize, GEMM_SMEM);
    cudaFuncSetAttribute((gemm_mma<2,1>), cudaFuncAttributeMaxDynamicSharedMemorySize, GEMM_SMEM);
    cudaFuncSetAttribute((gemm_mma<0,1>), cudaFuncAttributeMaxDynamicSharedMemorySize, GEMM_SMEM);

    static cudaStream_t s1 = nullptr, s2 = nullptr;
    static cudaEvent_t  efork = nullptr, ek = nullptr, ev = nullptr;
    if (!s1){
        cudaStreamCreateWithFlags(&s1, cudaStreamNonBlocking);
        cudaStreamCreateWithFlags(&s2, cudaStreamNonBlocking);
        cudaEventCreateWithFlags(&efork, cudaEventDisableTiming);
        cudaEventCreateWithFlags(&ek,    cudaEventDisableTiming);
        cudaEventCreateWithFlags(&ev,    cudaEventDisableTiming);
    }

    // splits (default stream)
    split_kernel<<<(MTOT*DM/4 + 255)/256, 256>>>(x, xh, xl, MTOT*DM);
    {
        dim3 gs((DM*DM/4 + 255)/256, 4);
        split4_hi_kernel<<<gs, 256>>>(Wq, Wk, Wv, Wo, wqh, wkh, wvh, woh);
    }

    // fork: K on s1, V on s2, Q stays on default stream
    cudaEventRecord(efork, 0);
    cudaStreamWaitEvent(s1, efork, 0);
    cudaStreamWaitEvent(s2, efork, 0);

    dim3 gg(DM/GBN, MTOT/GBM);   // (8, 32)
    const float qscale = 0.125f; // 1/sqrt(64)
    gemm_mma<1,2><<<gg, 256, GEMM_SMEM, 0 >>>(xh, xl, wqh, bq, nullptr, qhp, qlp, MTOT, DM, DM, qscale);
    gemm_mma<2,2><<<gg, 256, GEMM_SMEM, s1>>>(xh, xl, wkh, bk, nullptr, khp, nullptr, MTOT, DM, DM, 1.0f);
    gemm_mma<2,1><<<gg, 256, GEMM_SMEM, s2>>>(xh, nullptr, wvh, bv, nullptr, vhp, nullptr, MTOT, DM, DM, 1.0f);

    // join: attention needs Q (stream 0), K (s1), V (s2)
    cudaEventRecord(ek, s1);
    cudaEventRecord(ev, s2);
    cudaStreamWaitEvent(0, ek, 0);
    cudaStreamWaitEvent(0, ev, 0);

    dim3 ga(SEQ/BQ, NH, BATCH);  // (16, 16, 2)
    attn_mma<<<ga, 256, ATTN_SMEM>>>(qhp, qlp, khp, vhp, chp);

    gemm_mma<0,1><<<gg, 256, GEMM_SMEM>>>(chp, nullptr, woh, bo, out, nullptr, nullptr, MTOT, DM, DM, 1.0f);
}